// round 9
// baseline (speedup 1.0000x reference)
#include <cuda_runtime.h>
#include <cuda_bf16.h>

// Shapes (fixed by the problem)
#define B_   16
#define N_   64
#define C_   128
#define H_   64
#define W_   64
#define HW_  (H_ * W_)
#define NROI (B_ * N_)
#define OUTC 256
#define MAXG 16

// Scratch: z transposed to [B, H, W, C] and pooled features [NROI, C]
__device__ float g_zf[(size_t)B_ * HW_ * C_];     // 32 MB
__device__ float g_feats[NROI * C_];              // 512 KB

// ---------------------------------------------------------------------------
// Kernel 1: transpose z [B, C, HW] -> zf [B, HW, C]  (vectorized both sides)
// Side job: the first 128 blocks also zero g_feats.
// ---------------------------------------------------------------------------
__global__ void __launch_bounds__(256) transpose_kernel(const float* __restrict__ z) {
    __shared__ float tile[32][129];
    int b   = blockIdx.z;
    int hw0 = blockIdx.x * 128;
    int c0  = blockIdx.y * 32;
    int t   = threadIdx.x;

    int bid = blockIdx.x + 32 * (blockIdx.y + 4 * blockIdx.z);
    if (bid < (NROI * C_ / 4) / 256)   // 128 blocks
        reinterpret_cast<float4*>(g_feats)[bid * 256 + t] = make_float4(0.f, 0.f, 0.f, 0.f);

    const float* zb  = z    + (size_t)b * C_ * HW_;
    float*       zfb = g_zf + (size_t)b * HW_ * C_;

    #pragma unroll
    for (int it = 0; it < 4; ++it) {
        int j    = t + 256 * it;
        int row  = ((j >> 5) & 7) * 4 + ((j >> 3) & 3);   // 0..31 (channel)
        int col4 = ((j >> 8) & 3) * 8 + (j & 7);          // 0..31 (hw/4)
        float4 v = *(const float4*)(zb + (size_t)(c0 + row) * HW_ + hw0 + col4 * 4);
        tile[row][col4 * 4 + 0] = v.x;
        tile[row][col4 * 4 + 1] = v.y;
        tile[row][col4 * 4 + 2] = v.z;
        tile[row][col4 * 4 + 3] = v.w;
    }
    __syncthreads();
    #pragma unroll
    for (int it = 0; it < 4; ++it) {
        int j  = t + 256 * it;
        int hw = j >> 3;          // 0..127
        int cq = j & 7;           // 0..7 (channel/4)
        float4 v;
        v.x = tile[cq * 4 + 0][hw];
        v.y = tile[cq * 4 + 1][hw];
        v.z = tile[cq * 4 + 2][hw];
        v.w = tile[cq * 4 + 3][hw];
        *(float4*)(zfb + (size_t)(hw0 + hw) * C_ + c0 + cq * 4) = v;
    }
}

// ---------------------------------------------------------------------------
// Kernel 2: ROI-align. Block = one roi, 4 warps = 4 consecutive iy rows.
// Lane = channel-quad (float4). Fine granularity (<=16 samples per warp).
// ---------------------------------------------------------------------------
__global__ void __launch_bounds__(128) roi_kernel(const float* __restrict__ bboxes) {
    int roi  = blockIdx.x;                      // 0..1023
    int iy   = blockIdx.y * 4 + (threadIdx.x >> 5);
    int lane = threadIdx.x & 31;                // channel-quad
    int b    = roi >> 6;

    float4 box = reinterpret_cast<const float4*>(bboxes)[roi];
    float x1 = box.x * 0.125f - 0.5f;
    float y1 = box.y * 0.125f - 0.5f;
    float x2 = box.z * 0.125f - 0.5f;
    float y2 = box.w * 0.125f - 0.5f;

    float roi_w = x2 - x1, roi_h = y2 - y1;
    float gwf = fminf(fmaxf(ceilf(roi_w), 1.0f), (float)MAXG);
    float ghf = fminf(fmaxf(ceilf(roi_h), 1.0f), (float)MAXG);
    int gw = (int)gwf, gh = (int)ghf;
    if (iy >= gh) return;

    float bw = roi_w / gwf, bh = roi_h / ghf;

    float sy = y1 + ((float)iy + 0.5f) * bh;
    if (!(sy > -1.0f && sy < (float)H_)) return;     // row contributes 0
    float cy = fmaxf(sy, 0.0f);
    int yl = min((int)floorf(cy), H_ - 1);
    int yh = min(yl + 1, H_ - 1);
    float fy = (yl >= H_ - 1) ? 0.0f : (cy - (float)yl);
    float hy = 1.0f - fy;

    const float* zb = g_zf + (size_t)b * HW_ * C_ + lane * 4;
    const float* rl = zb + (size_t)yl * (W_ * C_);
    const float* rh = zb + (size_t)yh * (W_ * C_);

    float4 acc = make_float4(0.f, 0.f, 0.f, 0.f);

    #pragma unroll 4
    for (int ix = 0; ix < gw; ++ix) {
        float sx = x1 + ((float)ix + 0.5f) * bw;
        if (!(sx > -1.0f && sx < (float)W_)) continue;
        float cx = fmaxf(sx, 0.0f);
        int xl = min((int)floorf(cx), W_ - 1);
        int xh = min(xl + 1, W_ - 1);
        float fx = (xl >= W_ - 1) ? 0.0f : (cx - (float)xl);
        float hx = 1.0f - fx;

        float4 v11 = *(const float4*)(rl + xl * C_);
        float4 v12 = *(const float4*)(rl + xh * C_);
        float4 v21 = *(const float4*)(rh + xl * C_);
        float4 v22 = *(const float4*)(rh + xh * C_);
        float w11 = hy * hx, w12 = hy * fx, w21 = fy * hx, w22 = fy * fx;
        acc.x += w11 * v11.x + w12 * v12.x + w21 * v21.x + w22 * v22.x;
        acc.y += w11 * v11.y + w12 * v12.y + w21 * v21.y + w22 * v22.y;
        acc.z += w11 * v11.z + w12 * v12.z + w21 * v21.z + w22 * v22.z;
        acc.w += w11 * v11.w + w12 * v12.w + w21 * v21.w + w22 * v22.w;
    }

    float s = 1.0f / (gwf * ghf);
    float* dst = g_feats + roi * C_ + lane * 4;
    atomicAdd(dst + 0, acc.x * s);
    atomicAdd(dst + 1, acc.y * s);
    atomicAdd(dst + 2, acc.z * s);
    atomicAdd(dst + 3, acc.w * s);
}

// ---------------------------------------------------------------------------
// Kernel 3: out[m, o] = feats[m, :] . W[o, :] + b[o]
// Warp-uniform-W GEMM: block 128 thr = 4 warps; tile 32m x 16o.
// Warp w owns o-quad (o0 + 4w .. +3); lane = m. W rows are loaded with
// warp-UNIFORM LDG.128 (one wavefront, broadcast); feats come from a 16KB
// smem tile fsmT[k][m] (lanes span m -> conflict-free). No W staging barrier.
// Grid (32, 16) = 512 blocks.
// ---------------------------------------------------------------------------
#define MT 32
#define OTB 16
__global__ void __launch_bounds__(128) gemm_kernel(const float* __restrict__ Wm,
                                                   const float* __restrict__ bvec,
                                                   float* __restrict__ out) {
    __shared__ float fsmT[C_][MT + 1];   // [128][33] ~16.9 KB

    int m0   = blockIdx.x * MT;
    int o0   = blockIdx.y * OTB;
    int tid  = threadIdx.x;
    int lane = tid & 31;                 // m within tile
    int wrp  = tid >> 5;                 // 0..3 -> o-quad

    // Stage feats [MT][C] -> fsmT[k][m]: 8 float4 per thread, lanes span m.
    #pragma unroll
    for (int it = 0; it < (MT * C_ / 4) / 128; ++it) {   // 8 iters
        int idx = tid + 128 * it;
        int m   = idx & (MT - 1);
        int k4  = idx >> 5;                               // 0..31
        float4 v = *(const float4*)(g_feats + (size_t)(m0 + m) * C_ + k4 * 4);
        fsmT[k4 * 4 + 0][m] = v.x;
        fsmT[k4 * 4 + 1][m] = v.y;
        fsmT[k4 * 4 + 2][m] = v.z;
        fsmT[k4 * 4 + 3][m] = v.w;
    }
    __syncthreads();

    int o = o0 + wrp * 4;                // this warp's o-quad base
    const float* w0 = Wm + (size_t)(o + 0) * C_;
    const float* w1 = Wm + (size_t)(o + 1) * C_;
    const float* w2 = Wm + (size_t)(o + 2) * C_;
    const float* w3 = Wm + (size_t)(o + 3) * C_;

    float a0 = 0.f, a1 = 0.f, a2 = 0.f, a3 = 0.f;

    #pragma unroll 8
    for (int k = 0; k < C_; k += 4) {
        // warp-uniform loads: one 16B wavefront each, broadcast to all lanes
        float4 q0 = *(const float4*)(w0 + k);
        float4 q1 = *(const float4*)(w1 + k);
        float4 q2 = *(const float4*)(w2 + k);
        float4 q3 = *(const float4*)(w3 + k);
        float f0 = fsmT[k + 0][lane];
        float f1 = fsmT[k + 1][lane];
        float f2 = fsmT[k + 2][lane];
        float f3 = fsmT[k + 3][lane];
        a0 += f0 * q0.x + f1 * q0.y + f2 * q0.z + f3 * q0.w;
        a1 += f0 * q1.x + f1 * q1.y + f2 * q1.z + f3 * q1.w;
        a2 += f0 * q2.x + f1 * q2.y + f2 * q2.z + f3 * q2.w;
        a3 += f0 * q3.x + f1 * q3.y + f2 * q3.z + f3 * q3.w;
    }

    float4 bb = *(const float4*)(bvec + o);            // warp-uniform
    float4 r  = make_float4(a0 + bb.x, a1 + bb.y, a2 + bb.z, a3 + bb.w);
    *(float4*)(out + (size_t)(m0 + lane) * OUTC + o) = r;
}

// ---------------------------------------------------------------------------
extern "C" void kernel_launch(void* const* d_in, const int* in_sizes, int n_in,
                              void* d_out, int out_size) {
    const float* z      = (const float*)d_in[0];   // [B,C,H,W]
    const float* bboxes = (const float*)d_in[1];   // [B,N,4]
    const float* Wm     = (const float*)d_in[2];   // [OUTC,C]
    const float* bvec   = (const float*)d_in[3];   // [OUTC]
    float* out = (float*)d_out;                    // [B,N,OUTC]

    dim3 tgrid(HW_ / 128, C_ / 32, B_);            // (32, 4, 16)
    transpose_kernel<<<tgrid, 256>>>(z);
    roi_kernel<<<dim3(NROI, 4), 128>>>(bboxes);
    gemm_kernel<<<dim3(NROI / MT, OUTC / OTB), 128>>>(Wm, bvec, out);
}

// round 13
// speedup vs baseline: 1.5042x; 1.5042x over previous
#include <cuda_runtime.h>
#include <cuda_fp16.h>

// Shapes (fixed by the problem)
#define B_   16
#define N_   64
#define C_   128
#define H_   64
#define W_   64
#define HW_  (H_ * W_)
#define NROI (B_ * N_)
#define OUTC 256
#define MAXG 16

// Scratch: z transposed to [B, H, W, C] in fp16, pooled features [NROI, C] fp32
__device__ __half g_zh[(size_t)B_ * HW_ * C_];    // 16 MB
__device__ float  g_feats[NROI * C_];             // 512 KB

// ---------------------------------------------------------------------------
// Kernel 1: transpose z [B, C, HW] (f32) -> zh [B, HW, C] (f16)
// Side job: the first 128 blocks also zero g_feats.
// ---------------------------------------------------------------------------
__global__ void __launch_bounds__(256) transpose_kernel(const float* __restrict__ z) {
    __shared__ float tile[32][129];
    int b   = blockIdx.z;
    int hw0 = blockIdx.x * 128;
    int c0  = blockIdx.y * 32;
    int t   = threadIdx.x;

    int bid = blockIdx.x + 32 * (blockIdx.y + 4 * blockIdx.z);
    if (bid < (NROI * C_ / 4) / 256)   // 128 blocks
        reinterpret_cast<float4*>(g_feats)[bid * 256 + t] = make_float4(0.f, 0.f, 0.f, 0.f);

    const float* zb  = z    + (size_t)b * C_ * HW_;
    __half*      zhb = g_zh + (size_t)b * HW_ * C_;

    #pragma unroll
    for (int it = 0; it < 4; ++it) {
        int j    = t + 256 * it;
        int row  = ((j >> 5) & 7) * 4 + ((j >> 3) & 3);   // 0..31 (channel)
        int col4 = ((j >> 8) & 3) * 8 + (j & 7);          // 0..31 (hw/4)
        float4 v = *(const float4*)(zb + (size_t)(c0 + row) * HW_ + hw0 + col4 * 4);
        tile[row][col4 * 4 + 0] = v.x;
        tile[row][col4 * 4 + 1] = v.y;
        tile[row][col4 * 4 + 2] = v.z;
        tile[row][col4 * 4 + 3] = v.w;
    }
    __syncthreads();
    #pragma unroll
    for (int it = 0; it < 4; ++it) {
        int j  = t + 256 * it;
        int hw = j >> 3;          // 0..127
        int cq = j & 7;           // 0..7 (channel/4)
        __half2 h01 = __floats2half2_rn(tile[cq * 4 + 0][hw], tile[cq * 4 + 1][hw]);
        __half2 h23 = __floats2half2_rn(tile[cq * 4 + 2][hw], tile[cq * 4 + 3][hw]);
        uint2 u;
        u.x = *reinterpret_cast<unsigned*>(&h01);
        u.y = *reinterpret_cast<unsigned*>(&h23);
        *(uint2*)(zhb + (size_t)(hw0 + hw) * C_ + c0 + cq * 4) = u;   // 8B aligned store
    }
}

// ---------------------------------------------------------------------------
// Kernel 2: ROI-align. Block = one roi, 4 warps = 4 consecutive iy rows.
// Lane = channel-quad (4 fp16 = 8B LDG.64 per corner). fp32 accumulation.
// ---------------------------------------------------------------------------
__device__ __forceinline__ float2 ld_half4_lo_hi(const __half* p, float2& hi) {
    float2 raw = *(const float2*)p;                  // LDG.64
    __half2 ha = *reinterpret_cast<__half2*>(&raw.x);
    __half2 hb = *reinterpret_cast<__half2*>(&raw.y);
    hi = __half22float2(hb);
    return __half22float2(ha);
}

__global__ void __launch_bounds__(128) roi_kernel(const float* __restrict__ bboxes) {
    int roi  = blockIdx.x;                      // 0..1023
    int iy   = blockIdx.y * 4 + (threadIdx.x >> 5);
    int lane = threadIdx.x & 31;                // channel-quad
    int b    = roi >> 6;

    float4 box = reinterpret_cast<const float4*>(bboxes)[roi];
    float x1 = box.x * 0.125f - 0.5f;
    float y1 = box.y * 0.125f - 0.5f;
    float x2 = box.z * 0.125f - 0.5f;
    float y2 = box.w * 0.125f - 0.5f;

    float roi_w = x2 - x1, roi_h = y2 - y1;
    float gwf = fminf(fmaxf(ceilf(roi_w), 1.0f), (float)MAXG);
    float ghf = fminf(fmaxf(ceilf(roi_h), 1.0f), (float)MAXG);
    int gw = (int)gwf, gh = (int)ghf;
    if (iy >= gh) return;

    float bw = roi_w / gwf, bh = roi_h / ghf;

    float sy = y1 + ((float)iy + 0.5f) * bh;
    if (!(sy > -1.0f && sy < (float)H_)) return;     // row contributes 0
    float cy = fmaxf(sy, 0.0f);
    int yl = min((int)floorf(cy), H_ - 1);
    int yh = min(yl + 1, H_ - 1);
    float fy = (yl >= H_ - 1) ? 0.0f : (cy - (float)yl);
    float hy = 1.0f - fy;

    const __half* zb = g_zh + (size_t)b * HW_ * C_ + lane * 4;
    const __half* rl = zb + (size_t)yl * (W_ * C_);
    const __half* rh = zb + (size_t)yh * (W_ * C_);

    float4 acc = make_float4(0.f, 0.f, 0.f, 0.f);

    #pragma unroll 4
    for (int ix = 0; ix < gw; ++ix) {
        float sx = x1 + ((float)ix + 0.5f) * bw;
        if (!(sx > -1.0f && sx < (float)W_)) continue;
        float cx = fmaxf(sx, 0.0f);
        int xl = min((int)floorf(cx), W_ - 1);
        int xh = min(xl + 1, W_ - 1);
        float fx = (xl >= W_ - 1) ? 0.0f : (cx - (float)xl);
        float hx = 1.0f - fx;

        float2 a11h, a12h, a21h, a22h;
        float2 a11 = ld_half4_lo_hi(rl + xl * C_, a11h);
        float2 a12 = ld_half4_lo_hi(rl + xh * C_, a12h);
        float2 a21 = ld_half4_lo_hi(rh + xl * C_, a21h);
        float2 a22 = ld_half4_lo_hi(rh + xh * C_, a22h);
        float w11 = hy * hx, w12 = hy * fx, w21 = fy * hx, w22 = fy * fx;
        acc.x += w11 * a11.x  + w12 * a12.x  + w21 * a21.x  + w22 * a22.x;
        acc.y += w11 * a11.y  + w12 * a12.y  + w21 * a21.y  + w22 * a22.y;
        acc.z += w11 * a11h.x + w12 * a12h.x + w21 * a21h.x + w22 * a22h.x;
        acc.w += w11 * a11h.y + w12 * a12h.y + w21 * a21h.y + w22 * a22h.y;
    }

    float s = 1.0f / (gwf * ghf);
    float* dst = g_feats + roi * C_ + lane * 4;
    atomicAdd(dst + 0, acc.x * s);
    atomicAdd(dst + 1, acc.y * s);
    atomicAdd(dst + 2, acc.z * s);
    atomicAdd(dst + 3, acc.w * s);
}

// ---------------------------------------------------------------------------
// Kernel 3: out[m, o] = feats[m, :] . W[o, :] + b[o]
// Register-tiled GEMM (R4/R8 config): block tile 16m x 64o, thread 2m x 2o,
// 256 threads, grid (64, 4) = 256 blocks.
// ---------------------------------------------------------------------------
#define MT 16
#define OT 64
__global__ void __launch_bounds__(256) gemm_kernel(const float* __restrict__ Wm,
                                                   const float* __restrict__ bvec,
                                                   float* __restrict__ out) {
    __shared__ float Wt[C_][OT + 4];     // [128][68] ~34.8 KB
    __shared__ float fsmT[C_][MT];       // [128][16]   8 KB

    int m0  = blockIdx.x * MT;
    int o0  = blockIdx.y * OT;
    int tid = threadIdx.x;

    #pragma unroll
    for (int it = 0; it < (OT * C_ / 4) / 256; ++it) {
        int idx = tid + 256 * it;
        int o   = idx & (OT - 1);
        int k4  = idx >> 6;                               // 0..31
        float4 v = *(const float4*)(Wm + (size_t)(o0 + o) * C_ + k4 * 4);
        Wt[k4 * 4 + 0][o] = v.x;
        Wt[k4 * 4 + 1][o] = v.y;
        Wt[k4 * 4 + 2][o] = v.z;
        Wt[k4 * 4 + 3][o] = v.w;
    }
    #pragma unroll
    for (int it = 0; it < (MT * C_ / 4) / 256; ++it) {
        int idx = tid + 256 * it;
        int m   = idx & (MT - 1);
        int k4  = idx >> 4;                               // 0..31
        float4 v = *(const float4*)(g_feats + (size_t)(m0 + m) * C_ + k4 * 4);
        fsmT[k4 * 4 + 0][m] = v.x;
        fsmT[k4 * 4 + 1][m] = v.y;
        fsmT[k4 * 4 + 2][m] = v.z;
        fsmT[k4 * 4 + 3][m] = v.w;
    }
    __syncthreads();

    int oq = tid & 31;        // o-pair index 0..31
    int mq = tid >> 5;        // m-pair index 0..7 (warp-constant)

    float acc00 = 0.f, acc01 = 0.f, acc10 = 0.f, acc11 = 0.f;
    #pragma unroll 4
    for (int k = 0; k < C_; ++k) {
        float2 f = *(const float2*)&fsmT[k][mq * 2];   // warp broadcast
        float2 w = *(const float2*)&Wt[k][oq * 2];     // conflict-free
        acc00 += f.x * w.x;  acc01 += f.x * w.y;
        acc10 += f.y * w.x;  acc11 += f.y * w.y;
    }

    float2 bb = *(const float2*)(bvec + o0 + oq * 2);
    float2 r0 = make_float2(acc00 + bb.x, acc01 + bb.y);
    float2 r1 = make_float2(acc10 + bb.x, acc11 + bb.y);
    *(float2*)(out + (size_t)(m0 + mq * 2 + 0) * OUTC + o0 + oq * 2) = r0;
    *(float2*)(out + (size_t)(m0 + mq * 2 + 1) * OUTC + o0 + oq * 2) = r1;
}

// ---------------------------------------------------------------------------
extern "C" void kernel_launch(void* const* d_in, const int* in_sizes, int n_in,
                              void* d_out, int out_size) {
    const float* z      = (const float*)d_in[0];   // [B,C,H,W]
    const float* bboxes = (const float*)d_in[1];   // [B,N,4]
    const float* Wm     = (const float*)d_in[2];   // [OUTC,C]
    const float* bvec   = (const float*)d_in[3];   // [OUTC]
    float* out = (float*)d_out;                    // [B,N,OUTC]

    dim3 tgrid(HW_ / 128, C_ / 32, B_);            // (32, 4, 16)
    transpose_kernel<<<tgrid, 256>>>(z);
    roi_kernel<<<dim3(NROI, 4), 128>>>(bboxes);
    gemm_kernel<<<dim3(NROI / MT, OUTC / OT), 256>>>(Wm, bvec, out);
}

// round 17
// speedup vs baseline: 1.6684x; 1.1091x over previous
#include <cuda_runtime.h>
#include <cuda_fp16.h>

// Shapes (fixed by the problem)
#define B_   16
#define N_   64
#define C_   128
#define H_   64
#define W_   64
#define HW_  (H_ * W_)
#define NROI (B_ * N_)
#define OUTC 256
#define MAXG 16

// Scratch: z transposed to [B, H, W, C] in fp16, pooled features [NROI, C] fp32
__device__ __half g_zh[(size_t)B_ * HW_ * C_];    // 16 MB
__device__ float  g_feats[NROI * C_];             // 512 KB

// ---------------------------------------------------------------------------
// Kernel 1: transpose z [B, C, HW] (f32) -> zh [B, HW, C] (f16)
// Side job: the first 128 blocks also zero g_feats.
// ---------------------------------------------------------------------------
__global__ void __launch_bounds__(256) transpose_kernel(const float* __restrict__ z) {
    __shared__ float tile[32][129];
    int b   = blockIdx.z;
    int hw0 = blockIdx.x * 128;
    int c0  = blockIdx.y * 32;
    int t   = threadIdx.x;

    int bid = blockIdx.x + 32 * (blockIdx.y + 4 * blockIdx.z);
    if (bid < (NROI * C_ / 4) / 256)   // 128 blocks
        reinterpret_cast<float4*>(g_feats)[bid * 256 + t] = make_float4(0.f, 0.f, 0.f, 0.f);

    const float* zb  = z    + (size_t)b * C_ * HW_;
    __half*      zhb = g_zh + (size_t)b * HW_ * C_;

    #pragma unroll
    for (int it = 0; it < 4; ++it) {
        int j    = t + 256 * it;
        int row  = ((j >> 5) & 7) * 4 + ((j >> 3) & 3);   // 0..31 (channel)
        int col4 = ((j >> 8) & 3) * 8 + (j & 7);          // 0..31 (hw/4)
        float4 v = *(const float4*)(zb + (size_t)(c0 + row) * HW_ + hw0 + col4 * 4);
        tile[row][col4 * 4 + 0] = v.x;
        tile[row][col4 * 4 + 1] = v.y;
        tile[row][col4 * 4 + 2] = v.z;
        tile[row][col4 * 4 + 3] = v.w;
    }
    __syncthreads();
    #pragma unroll
    for (int it = 0; it < 2; ++it) {
        int j   = t + 256 * it;
        int cq8 = j & 3;          // channel-octet 0..3
        int hw  = j >> 2;         // 0..127
        int r0  = cq8 * 8;
        __half2 h0 = __floats2half2_rn(tile[r0 + 0][hw], tile[r0 + 1][hw]);
        __half2 h1 = __floats2half2_rn(tile[r0 + 2][hw], tile[r0 + 3][hw]);
        __half2 h2 = __floats2half2_rn(tile[r0 + 4][hw], tile[r0 + 5][hw]);
        __half2 h3 = __floats2half2_rn(tile[r0 + 6][hw], tile[r0 + 7][hw]);
        uint4 u;
        u.x = *reinterpret_cast<unsigned*>(&h0);
        u.y = *reinterpret_cast<unsigned*>(&h1);
        u.z = *reinterpret_cast<unsigned*>(&h2);
        u.w = *reinterpret_cast<unsigned*>(&h3);
        *(uint4*)(zhb + (size_t)(hw0 + hw) * C_ + c0 + r0) = u;   // 16B store
    }
}

// ---------------------------------------------------------------------------
// Kernel 2: ROI-align. Block = one roi, 4 warps = 4 consecutive iy rows.
// Lane = channel-quad (4 fp16 = 8B LDG.64 per corner). fp32 accumulation.
// ---------------------------------------------------------------------------
__device__ __forceinline__ float2 ld_half4_lo_hi(const __half* p, float2& hi) {
    float2 raw = *(const float2*)p;                  // LDG.64
    __half2 ha = *reinterpret_cast<__half2*>(&raw.x);
    __half2 hb = *reinterpret_cast<__half2*>(&raw.y);
    hi = __half22float2(hb);
    return __half22float2(ha);
}

__global__ void __launch_bounds__(128) roi_kernel(const float* __restrict__ bboxes) {
    int roi  = blockIdx.x;                      // 0..1023
    int iy   = blockIdx.y * 4 + (threadIdx.x >> 5);
    int lane = threadIdx.x & 31;                // channel-quad
    int b    = roi >> 6;

    float4 box = reinterpret_cast<const float4*>(bboxes)[roi];
    float x1 = box.x * 0.125f - 0.5f;
    float y1 = box.y * 0.125f - 0.5f;
    float x2 = box.z * 0.125f - 0.5f;
    float y2 = box.w * 0.125f - 0.5f;

    float roi_w = x2 - x1, roi_h = y2 - y1;
    float gwf = fminf(fmaxf(ceilf(roi_w), 1.0f), (float)MAXG);
    float ghf = fminf(fmaxf(ceilf(roi_h), 1.0f), (float)MAXG);
    int gw = (int)gwf, gh = (int)ghf;
    if (iy >= gh) return;

    float bw = roi_w / gwf, bh = roi_h / ghf;

    float sy = y1 + ((float)iy + 0.5f) * bh;
    if (!(sy > -1.0f && sy < (float)H_)) return;     // row contributes 0
    float cy = fmaxf(sy, 0.0f);
    int yl = min((int)floorf(cy), H_ - 1);
    int yh = min(yl + 1, H_ - 1);
    float fy = (yl >= H_ - 1) ? 0.0f : (cy - (float)yl);
    float hy = 1.0f - fy;

    const __half* zb = g_zh + (size_t)b * HW_ * C_ + lane * 4;
    const __half* rl = zb + (size_t)yl * (W_ * C_);
    const __half* rh = zb + (size_t)yh * (W_ * C_);

    float4 acc = make_float4(0.f, 0.f, 0.f, 0.f);

    #pragma unroll 4
    for (int ix = 0; ix < gw; ++ix) {
        float sx = x1 + ((float)ix + 0.5f) * bw;
        if (!(sx > -1.0f && sx < (float)W_)) continue;
        float cx = fmaxf(sx, 0.0f);
        int xl = min((int)floorf(cx), W_ - 1);
        int xh = min(xl + 1, W_ - 1);
        float fx = (xl >= W_ - 1) ? 0.0f : (cx - (float)xl);
        float hx = 1.0f - fx;

        float2 a11h, a12h, a21h, a22h;
        float2 a11 = ld_half4_lo_hi(rl + xl * C_, a11h);
        float2 a12 = ld_half4_lo_hi(rl + xh * C_, a12h);
        float2 a21 = ld_half4_lo_hi(rh + xl * C_, a21h);
        float2 a22 = ld_half4_lo_hi(rh + xh * C_, a22h);
        float w11 = hy * hx, w12 = hy * fx, w21 = fy * hx, w22 = fy * fx;
        acc.x += w11 * a11.x  + w12 * a12.x  + w21 * a21.x  + w22 * a22.x;
        acc.y += w11 * a11.y  + w12 * a12.y  + w21 * a21.y  + w22 * a22.y;
        acc.z += w11 * a11h.x + w12 * a12h.x + w21 * a21h.x + w22 * a22h.x;
        acc.w += w11 * a11h.y + w12 * a12h.y + w21 * a21h.y + w22 * a22h.y;
    }

    float s = 1.0f / (gwf * ghf);
    float* dst = g_feats + roi * C_ + lane * 4;
    atomicAdd(dst + 0, acc.x * s);
    atomicAdd(dst + 1, acc.y * s);
    atomicAdd(dst + 2, acc.z * s);
    atomicAdd(dst + 3, acc.w * s);
}

// ---------------------------------------------------------------------------
// Kernel 3: out[m, o] = feats[m, :] . W[o, :] + b[o]
// Register-tiled GEMM: block tile 32m x 64o, thread tile 2m x 4o, 256 thr.
// Grid (32, 4) = 128 blocks = ONE wave on 148 SMs (no wave quantization).
// fsmT stride = 32 floats (128 B): all float2/float4 accesses aligned.
// ---------------------------------------------------------------------------
#define MT 32
#define OT 64
__global__ void __launch_bounds__(256) gemm_kernel(const float* __restrict__ Wm,
                                                   const float* __restrict__ bvec,
                                                   float* __restrict__ out) {
    __shared__ float Wt[C_][OT + 4];      // [128][68] ~34.8 KB (272B rows, 16B-mult)
    __shared__ float fsmT[C_][MT];        // [128][32]  16 KB (128B rows, aligned)

    int m0  = blockIdx.x * MT;
    int o0  = blockIdx.y * OT;
    int tid = threadIdx.x;

    // Stage W slice [OT][C] -> Wt[k][o]  (8 iters of 256 float4)
    #pragma unroll
    for (int it = 0; it < (OT * C_ / 4) / 256; ++it) {
        int idx = tid + 256 * it;
        int o   = idx & (OT - 1);
        int k4  = idx >> 6;                               // 0..31
        float4 v = *(const float4*)(Wm + (size_t)(o0 + o) * C_ + k4 * 4);
        Wt[k4 * 4 + 0][o] = v.x;
        Wt[k4 * 4 + 1][o] = v.y;
        Wt[k4 * 4 + 2][o] = v.z;
        Wt[k4 * 4 + 3][o] = v.w;
    }
    // Stage feats [MT][C] -> fsmT[k][m]  (4 iters; lanes span m -> bank = m)
    #pragma unroll
    for (int it = 0; it < (MT * C_ / 4) / 256; ++it) {
        int idx = tid + 256 * it;
        int m   = idx & (MT - 1);
        int k4  = idx >> 5;                               // 0..31
        float4 v = *(const float4*)(g_feats + (size_t)(m0 + m) * C_ + k4 * 4);
        fsmT[k4 * 4 + 0][m] = v.x;
        fsmT[k4 * 4 + 1][m] = v.y;
        fsmT[k4 * 4 + 2][m] = v.z;
        fsmT[k4 * 4 + 3][m] = v.w;
    }
    __syncthreads();

    int oq = tid & 15;        // o-quad index 0..15  (o = oq*4)
    int mq = tid >> 4;        // m-pair index 0..15  (m = mq*2)

    float a00 = 0.f, a01 = 0.f, a02 = 0.f, a03 = 0.f;
    float a10 = 0.f, a11 = 0.f, a12 = 0.f, a13 = 0.f;
    #pragma unroll 4
    for (int k = 0; k < C_; ++k) {
        float2 f = *(const float2*)&fsmT[k][mq * 2];   // 2-addr broadcast, aligned
        float4 w = *(const float4*)&Wt[k][oq * 4];     // 64 consec words, dedup
        a00 += f.x * w.x;  a01 += f.x * w.y;  a02 += f.x * w.z;  a03 += f.x * w.w;
        a10 += f.y * w.x;  a11 += f.y * w.y;  a12 += f.y * w.z;  a13 += f.y * w.w;
    }

    float4 bb = *(const float4*)(bvec + o0 + oq * 4);
    float4 r0 = make_float4(a00 + bb.x, a01 + bb.y, a02 + bb.z, a03 + bb.w);
    float4 r1 = make_float4(a10 + bb.x, a11 + bb.y, a12 + bb.z, a13 + bb.w);
    *(float4*)(out + (size_t)(m0 + mq * 2 + 0) * OUTC + o0 + oq * 4) = r0;
    *(float4*)(out + (size_t)(m0 + mq * 2 + 1) * OUTC + o0 + oq * 4) = r1;
}

// ---------------------------------------------------------------------------
extern "C" void kernel_launch(void* const* d_in, const int* in_sizes, int n_in,
                              void* d_out, int out_size) {
    const float* z      = (const float*)d_in[0];   // [B,C,H,W]
    const float* bboxes = (const float*)d_in[1];   // [B,N,4]
    const float* Wm     = (const float*)d_in[2];   // [OUTC,C]
    const float* bvec   = (const float*)d_in[3];   // [OUTC]
    float* out = (float*)d_out;                    // [B,N,OUTC]

    dim3 tgrid(HW_ / 128, C_ / 32, B_);            // (32, 4, 16)
    transpose_kernel<<<tgrid, 256>>>(z);
    roi_kernel<<<dim3(NROI, 4), 128>>>(bboxes);
    gemm_kernel<<<dim3(NROI / MT, OUTC / OT), 256>>>(Wm, bvec, out);
}